// round 2
// baseline (speedup 1.0000x reference)
#include <cuda_runtime.h>
#include <math.h>

#define Bsz 64
#define DFd 768
#define Fd  676
#define Cd  3129
#define DWd 300
#define DTd 1024
#define TK  10

// ---------------- device scratch (static, allocation-free) ----------------
__device__ int   g_topk[Bsz*TK];
__device__ float g_emb [Bsz*TK*DWd];
__device__ float g_cls1[Bsz*TK*DTd];
__device__ float g_cls [Bsz*TK*DTd];
__device__ float g_v   [(size_t)Bsz*Fd*DTd];   // 177 MB
__device__ float g_s   [Bsz*Fd*TK];
__device__ float g_bap [Bsz*DTd];
__device__ float g_bap2[Bsz*DTd];

// ---------------- top-k (matches jax.lax.top_k: ties -> lowest index) -----
__global__ void topk_kernel(const float* __restrict__ logits) {
    int b = blockIdx.x;
    const float* row = logits + b*Cd;
    __shared__ float sv[256];
    __shared__ int   si[256];
    __shared__ int   chosen[TK];
    int tid = threadIdx.x;
    for (int sel = 0; sel < TK; sel++) {
        float best = -INFINITY; int bi = 1 << 30;
        for (int i = tid; i < Cd; i += 256) {
            bool skip = false;
            for (int j = 0; j < sel; j++) if (chosen[j] == i) skip = true;
            if (skip) continue;
            float v = row[i];
            if (v > best || (v == best && i < bi)) { best = v; bi = i; }
        }
        sv[tid] = best; si[tid] = bi;
        __syncthreads();
        for (int s = 128; s > 0; s >>= 1) {
            if (tid < s) {
                if (sv[tid+s] > sv[tid] || (sv[tid+s] == sv[tid] && si[tid+s] < si[tid])) {
                    sv[tid] = sv[tid+s]; si[tid] = si[tid+s];
                }
            }
            __syncthreads();
        }
        if (tid == 0) chosen[sel] = si[0];
        __syncthreads();
    }
    if (tid < TK) g_topk[b*TK + tid] = chosen[tid];
}

// ---------------- gather + mean-pool word embeddings -----------------------
__global__ void gather_emb_kernel(const int* __restrict__ table,
                                  const float* __restrict__ w2v) {
    int bk = blockIdx.x;                 // 0..639
    int c  = g_topk[bk];
    int i0 = table[c*4+0], i1 = table[c*4+1], i2 = table[c*4+2], i3 = table[c*4+3];
    for (int d = threadIdx.x; d < DWd; d += blockDim.x)
        g_emb[bk*DWd + d] = 0.25f*(w2v[(size_t)i0*DWd+d] + w2v[(size_t)i1*DWd+d]
                                 + w2v[(size_t)i2*DWd+d] + w2v[(size_t)i3*DWd+d]);
}

// ---------------- generic fp32 GEMM: C = relu?(A @ B + bias) ---------------
// AT=true : A stored [K, M] (k-major rows, m contiguous)  -- used for ftm^T
//           batched via blockIdx.z (A stride K*M, C stride M*N)
// AT=false: A stored [M, K] row-major
template<bool AT>
__global__ void gemm_kernel(const float* __restrict__ A, const float* __restrict__ Bm,
                            const float* __restrict__ bias, float* __restrict__ Cm,
                            int Md, int Nd, int Kd, int relu)
{
    __shared__ float As[16][68];
    __shared__ float Bs[16][68];
    const float* Ab = A;
    float* Cb = Cm;
    if (AT) {
        Ab = A  + (size_t)blockIdx.z * Kd * Md;
        Cb = Cm + (size_t)blockIdx.z * Md * Nd;
    }
    int m0 = blockIdx.y * 64, n0 = blockIdx.x * 64;
    int tid = threadIdx.x;
    int tx = tid & 15, ty = tid >> 4;
    float acc[4][4] = {};

    for (int k0 = 0; k0 < Kd; k0 += 16) {
        if (AT) {
            int mm = tid & 63, kk0 = tid >> 6;
            #pragma unroll
            for (int r = 0; r < 4; r++) {
                int kk = kk0 + r*4;
                int k = k0 + kk, m = m0 + mm;
                As[kk][mm] = (k < Kd && m < Md) ? Ab[(size_t)k*Md + m] : 0.f;
            }
        } else {
            int kk = tid & 15, mm0 = tid >> 4;
            #pragma unroll
            for (int r = 0; r < 4; r++) {
                int mm = mm0 + r*16;
                int k = k0 + kk, m = m0 + mm;
                As[kk][mm] = (k < Kd && m < Md) ? Ab[(size_t)m*Kd + k] : 0.f;
            }
        }
        {
            int nn = tid & 63, kk0 = tid >> 6;
            #pragma unroll
            for (int r = 0; r < 4; r++) {
                int kk = kk0 + r*4;
                int k = k0 + kk, n = n0 + nn;
                Bs[kk][nn] = (k < Kd && n < Nd) ? Bm[(size_t)k*Nd + n] : 0.f;
            }
        }
        __syncthreads();
        #pragma unroll
        for (int kk = 0; kk < 16; kk++) {
            float4 a4 = *(const float4*)&As[kk][ty*4];
            float4 b4 = *(const float4*)&Bs[kk][tx*4];
            float av[4] = {a4.x, a4.y, a4.z, a4.w};
            float bv[4] = {b4.x, b4.y, b4.z, b4.w};
            #pragma unroll
            for (int i = 0; i < 4; i++)
                #pragma unroll
                for (int j = 0; j < 4; j++)
                    acc[i][j] += av[i] * bv[j];
        }
        __syncthreads();
    }
    #pragma unroll
    for (int i = 0; i < 4; i++) {
        int m = m0 + ty*4 + i;
        if (m >= Md) continue;
        #pragma unroll
        for (int j = 0; j < 4; j++) {
            int n = n0 + tx*4 + j;
            if (n >= Nd) continue;
            float c = acc[i][j] + bias[n];
            if (relu) c = fmaxf(c, 0.f);
            Cb[(size_t)m*Nd + n] = c;
        }
    }
}

// ---------------- attention scores: s[b,f,k] = v[b,f,:] . cls[b,k,:] -------
// Each warp handles 4 consecutive f rows (register reuse of cls smem reads).
__global__ void scores_kernel() {
    int b = blockIdx.y;
    __shared__ float cls_s[TK*DTd];      // 40 KB
    for (int i = threadIdx.x; i < TK*DTd; i += 256)
        cls_s[i] = g_cls[b*TK*DTd + i];
    __syncthreads();
    int w = threadIdx.x >> 5, lane = threadIdx.x & 31;
    int f0 = (blockIdx.x*8 + w) * 4;
    float acc[4][TK];
    #pragma unroll
    for (int j = 0; j < 4; j++)
        #pragma unroll
        for (int k = 0; k < TK; k++) acc[j][k] = 0.f;
    const float* vb = g_v + (size_t)b*Fd*DTd;
    for (int i = 0; i < 32; i++) {
        int t = lane + 32*i;
        float vv[4];
        #pragma unroll
        for (int j = 0; j < 4; j++)
            vv[j] = (f0+j < Fd) ? vb[(size_t)(f0+j)*DTd + t] : 0.f;
        #pragma unroll
        for (int k = 0; k < TK; k++) {
            float c = cls_s[k*DTd + t];
            #pragma unroll
            for (int j = 0; j < 4; j++) acc[j][k] += vv[j] * c;
        }
    }
    #pragma unroll
    for (int j = 0; j < 4; j++) {
        #pragma unroll
        for (int k = 0; k < TK; k++) {
            float r = acc[j][k];
            #pragma unroll
            for (int o = 16; o; o >>= 1) r += __shfl_xor_sync(0xffffffffu, r, o);
            if (lane == 0 && f0+j < Fd)
                g_s[((size_t)b*Fd + f0 + j)*TK + k] = r;
        }
    }
}

// ---------------- softmax over f per (b,k), in place -----------------------
__global__ void softmax_kernel() {
    int b = blockIdx.y, k = blockIdx.x;
    float* base = g_s + (size_t)b*Fd*TK + k;
    __shared__ float red[256];
    int tid = threadIdx.x;
    float mx = -INFINITY;
    for (int f = tid; f < Fd; f += 256) mx = fmaxf(mx, base[f*TK]);
    red[tid] = mx; __syncthreads();
    for (int s = 128; s > 0; s >>= 1) {
        if (tid < s) red[tid] = fmaxf(red[tid], red[tid+s]);
        __syncthreads();
    }
    mx = red[0]; __syncthreads();
    float sum = 0.f;
    for (int f = tid; f < Fd; f += 256) {
        float e = expf(base[f*TK] - mx);
        base[f*TK] = e;
        sum += e;
    }
    red[tid] = sum; __syncthreads();
    for (int s = 128; s > 0; s >>= 1) {
        if (tid < s) red[tid] += red[tid+s];
        __syncthreads();
    }
    float inv = 1.f / red[0];
    for (int f = tid; f < Fd; f += 256) base[f*TK] *= inv;
}

// ---------------- bap[b,d] = sum_k cls[b,k,d] * sum_f att[b,f,k]*v[b,f,d] --
__global__ void bap_kernel() {
    int b = blockIdx.y;
    int d = blockIdx.x*256 + threadIdx.x;     // 0..1023
    __shared__ float att_s[Fd*12];            // padded to 12 for aligned float4
    for (int i = threadIdx.x; i < Fd*12; i += 256) {
        int f = i / 12, k = i % 12;
        att_s[i] = (k < TK) ? g_s[((size_t)b*Fd + f)*TK + k] : 0.f;
    }
    __syncthreads();
    float acc[TK] = {};
    const float* vb = g_v + (size_t)b*Fd*DTd + d;
    for (int f = 0; f < Fd; f++) {
        float vv = vb[(size_t)f*DTd];
        const float4* ap = (const float4*)&att_s[f*12];
        float4 a0 = ap[0], a1 = ap[1], a2 = ap[2];
        acc[0] += vv*a0.x; acc[1] += vv*a0.y; acc[2] += vv*a0.z; acc[3] += vv*a0.w;
        acc[4] += vv*a1.x; acc[5] += vv*a1.y; acc[6] += vv*a1.z; acc[7] += vv*a1.w;
        acc[8] += vv*a2.x; acc[9] += vv*a2.y;
    }
    float r = 0.f;
    #pragma unroll
    for (int k = 0; k < TK; k++)
        r += acc[k] * g_cls[((size_t)b*TK + k)*DTd + d];
    g_bap[b*DTd + d] = r;
}

// ---------------- final FC (DT->K) + scatter into [B, C] output ------------
__global__ void fc_scatter_kernel(const float* __restrict__ W_fc,
                                  const float* __restrict__ b_fc,
                                  float* __restrict__ out) {
    int b = blockIdx.x;
    int wid = threadIdx.x >> 5, lane = threadIdx.x & 31;   // 10 warps
    if (wid < TK) {
        float s = 0.f;
        for (int d = lane; d < DTd; d += 32)
            s += g_bap2[b*DTd + d] * W_fc[d*TK + wid];
        #pragma unroll
        for (int o = 16; o; o >>= 1) s += __shfl_xor_sync(0xffffffffu, s, o);
        if (lane == 0)
            out[(size_t)b*Cd + g_topk[b*TK + wid]] = s + b_fc[wid];
    }
}

// ---------------- launch ----------------------------------------------------
extern "C" void kernel_launch(void* const* d_in, const int* in_sizes, int n_in,
                              void* d_out, int out_size) {
    const float* ftm    = (const float*)d_in[0];
    const float* logits = (const float*)d_in[1];
    /* d_in[2] = labels (unused by reference) */
    const int*   table  = (const int*)  d_in[3];
    const float* w2v    = (const float*)d_in[4];
    const float* W_emb  = (const float*)d_in[5];
    const float* b_emb  = (const float*)d_in[6];
    const float* W_cls  = (const float*)d_in[7];
    const float* b_cls  = (const float*)d_in[8];
    const float* W_v    = (const float*)d_in[9];
    const float* b_v    = (const float*)d_in[10];
    const float* W_bap  = (const float*)d_in[11];
    const float* b_bap  = (const float*)d_in[12];
    const float* W_fc   = (const float*)d_in[13];
    const float* b_fc   = (const float*)d_in[14];
    float* out = (float*)d_out;

    float *p_emb, *p_cls1, *p_cls, *p_v, *p_bap, *p_bap2;
    cudaGetSymbolAddress((void**)&p_emb,  g_emb);
    cudaGetSymbolAddress((void**)&p_cls1, g_cls1);
    cudaGetSymbolAddress((void**)&p_cls,  g_cls);
    cudaGetSymbolAddress((void**)&p_v,    g_v);
    cudaGetSymbolAddress((void**)&p_bap,  g_bap);
    cudaGetSymbolAddress((void**)&p_bap2, g_bap2);

    cudaMemsetAsync(d_out, 0, (size_t)out_size * sizeof(float), 0);

    topk_kernel<<<Bsz, 256>>>(logits);
    gather_emb_kernel<<<Bsz*TK, 128>>>(table, w2v);

    // cls1 = relu(emb @ W_emb + b_emb)       [640 x 1024, K=300]
    gemm_kernel<false><<<dim3(16, 10, 1), 256>>>(p_emb,  W_emb, b_emb, p_cls1, Bsz*TK, DTd, DWd, 1);
    // cls  = relu(cls1 @ W_cls + b_cls)      [640 x 1024, K=1024]
    gemm_kernel<false><<<dim3(16, 10, 1), 256>>>(p_cls1, W_cls, b_cls, p_cls,  Bsz*TK, DTd, DTd, 1);
    // v = relu(ftm^T @ W_v + b_v)            64 x [676 x 1024, K=768]  (dominant)
    gemm_kernel<true><<<dim3(16, 11, Bsz), 256>>>(ftm, W_v, b_v, p_v, Fd, DTd, DFd, 1);

    scores_kernel <<<dim3(22, Bsz), 256>>>();
    softmax_kernel<<<dim3(TK, Bsz), 256>>>();
    bap_kernel    <<<dim3(4,  Bsz), 256>>>();

    // bap2 = relu(bap @ W_bap + b_bap)       [64 x 1024, K=1024]
    gemm_kernel<false><<<dim3(16, 1, 1), 256>>>(p_bap, W_bap, b_bap, p_bap2, Bsz, DTd, DTd, 1);

    fc_scatter_kernel<<<Bsz, 320>>>(W_fc, b_fc, out);
}

// round 4
// speedup vs baseline: 1.6562x; 1.6562x over previous
#include <cuda_runtime.h>
#include <cuda_fp16.h>
#include <math.h>
#include <stdint.h>

#define Bsz 64
#define DFd 768
#define Fd  676
#define Cd  3129
#define DWd 300
#define DTd 1024
#define TK  10

// ---------------- device scratch (static, allocation-free) ----------------
__device__ int   g_topk[Bsz*TK];
__device__ float g_emb [Bsz*TK*DWd];
__device__ float g_cls1[Bsz*TK*DTd];
__device__ float g_cls [Bsz*TK*DTd];
__device__ float g_v   [(size_t)Bsz*Fd*DTd];   // 177 MB
__device__ float g_s   [Bsz*Fd*TK];
__device__ float g_bap [Bsz*DTd];
__device__ float g_bap2[Bsz*DTd];

// ================= fp16x2-split tensor-core GEMM (mma.sync HMMA) ==========
// C[m][n] = relu( sum_k A[m][k] * B[k][n] + bias[n] ),  N = 1024 fixed.
// AT=1: A stored [K][M] (m contiguous) and batched over blockIdx.z.
// Each fp32 x is split x = hi + lo (fp16); product emulated by
// hi*hi + hi*lo + lo*hi accumulated in fp32 (error ~2^-22).
#define SM_STRIDE 34          // halves per row (17 words -> conflict-free)
#define AHo 0
#define ALo (128*SM_STRIDE)
#define BHo (2*128*SM_STRIDE)
#define BLo (3*128*SM_STRIDE)

__device__ __forceinline__ void mma16816(float* c, const uint32_t* a, const uint32_t* b) {
    asm volatile(
        "mma.sync.aligned.m16n8k16.row.col.f32.f16.f16.f32 "
        "{%0,%1,%2,%3}, {%4,%5,%6,%7}, {%8,%9}, {%0,%1,%2,%3};"
        : "+f"(c[0]), "+f"(c[1]), "+f"(c[2]), "+f"(c[3])
        : "r"(a[0]), "r"(a[1]), "r"(a[2]), "r"(a[3]), "r"(b[0]), "r"(b[1]));
}
__device__ __forceinline__ void split2(float x, __half& h, __half& l) {
    h = __float2half_rn(x);
    l = __float2half_rn(x - __half2float(h));
}

template<int AT>
__global__ void __launch_bounds__(256)
tgemm_kernel(const float* __restrict__ A, const float* __restrict__ Bm,
             const float* __restrict__ bias, float* __restrict__ Cm,
             int Md, int Kd)
{
    __shared__ __half sm[4*128*SM_STRIDE];   // 34816 B
    int tid  = threadIdx.x;
    int w    = tid >> 5, lane = tid & 31;
    int m0   = blockIdx.y * 128, n0 = blockIdx.x * 128;
    const float* Ab = A;
    float* Cb = Cm;
    if (AT) {
        Ab = A  + (size_t)blockIdx.z * Kd * Md;
        Cb = Cm + (size_t)blockIdx.z * Md * DTd;
    }
    int nk = (Kd + 31) / 32;

    float pa[16], pb[16];
    // ---- prologue: load chunk 0 ----
    {
        int k0 = 0;
        if (AT) {
            #pragma unroll
            for (int i = 0; i < 4; i++) {
                int k = 8*i + w;
                const float* col = Ab + (size_t)(k0 + k) * Md + m0;
                #pragma unroll
                for (int j = 0; j < 4; j++) {
                    int fl = lane + 32*j;
                    pa[i*4+j] = (k0+k < Kd && m0+fl < Md) ? col[fl] : 0.f;
                }
            }
        } else {
            #pragma unroll
            for (int rr = 0; rr < 16; rr++) {
                int m = m0 + w*16 + rr;
                pa[rr] = (m < Md && k0+lane < Kd) ? Ab[(size_t)m*Kd + k0 + lane] : 0.f;
            }
        }
        #pragma unroll
        for (int i = 0; i < 4; i++) {
            int k = 8*i + w;
            const float* col = Bm + (size_t)(k0 + k) * DTd + n0;
            #pragma unroll
            for (int j = 0; j < 4; j++)
                pb[i*4+j] = (k0+k < Kd) ? col[lane + 32*j] : 0.f;
        }
    }
    // store chunk 0
    {
        if (AT) {
            #pragma unroll
            for (int i = 0; i < 4; i++) {
                int k = 8*i + w;
                #pragma unroll
                for (int j = 0; j < 4; j++) {
                    int fl = lane + 32*j;
                    __half h, l; split2(pa[i*4+j], h, l);
                    sm[AHo + fl*SM_STRIDE + k] = h;
                    sm[ALo + fl*SM_STRIDE + k] = l;
                }
            }
        } else {
            #pragma unroll
            for (int rr = 0; rr < 16; rr++) {
                __half h, l; split2(pa[rr], h, l);
                sm[AHo + (w*16+rr)*SM_STRIDE + lane] = h;
                sm[ALo + (w*16+rr)*SM_STRIDE + lane] = l;
            }
        }
        #pragma unroll
        for (int i = 0; i < 4; i++) {
            int k = 8*i + w;
            #pragma unroll
            for (int j = 0; j < 4; j++) {
                int nl = lane + 32*j;
                __half h, l; split2(pb[i*4+j], h, l);
                sm[BHo + nl*SM_STRIDE + k] = h;
                sm[BLo + nl*SM_STRIDE + k] = l;
            }
        }
    }
    __syncthreads();

    int wm = (w & 3) * 32;          // warp m offset in tile
    int wn = (w >> 2) * 64;         // warp n offset in tile
    float acc[2][8][4];
    #pragma unroll
    for (int mt = 0; mt < 2; mt++)
        #pragma unroll
        for (int nt = 0; nt < 8; nt++)
            #pragma unroll
            for (int q = 0; q < 4; q++) acc[mt][nt][q] = 0.f;

    for (int kb = 0; kb < nk; kb++) {
        // ---- prefetch next chunk into registers ----
        if (kb + 1 < nk) {
            int k0 = (kb + 1) * 32;
            if (AT) {
                #pragma unroll
                for (int i = 0; i < 4; i++) {
                    int k = 8*i + w;
                    const float* col = Ab + (size_t)(k0 + k) * Md + m0;
                    #pragma unroll
                    for (int j = 0; j < 4; j++) {
                        int fl = lane + 32*j;
                        pa[i*4+j] = (k0+k < Kd && m0+fl < Md) ? col[fl] : 0.f;
                    }
                }
            } else {
                #pragma unroll
                for (int rr = 0; rr < 16; rr++) {
                    int m = m0 + w*16 + rr;
                    pa[rr] = (m < Md && k0+lane < Kd) ? Ab[(size_t)m*Kd + k0 + lane] : 0.f;
                }
            }
            #pragma unroll
            for (int i = 0; i < 4; i++) {
                int k = 8*i + w;
                const float* col = Bm + (size_t)(k0 + k) * DTd + n0;
                #pragma unroll
                for (int j = 0; j < 4; j++)
                    pb[i*4+j] = (k0+k < Kd) ? col[lane + 32*j] : 0.f;
            }
        }
        // ---- compute on current smem chunk ----
        #pragma unroll
        for (int ks = 0; ks < 32; ks += 16) {
            uint32_t ah[2][4], al[2][4];
            #pragma unroll
            for (int mt = 0; mt < 2; mt++) {
                int base = (wm + mt*16 + (lane >> 2)) * SM_STRIDE + ks + (lane & 3) * 2;
                ah[mt][0] = *(const uint32_t*)&sm[AHo + base];
                ah[mt][1] = *(const uint32_t*)&sm[AHo + base + 8*SM_STRIDE];
                ah[mt][2] = *(const uint32_t*)&sm[AHo + base + 8];
                ah[mt][3] = *(const uint32_t*)&sm[AHo + base + 8*SM_STRIDE + 8];
                al[mt][0] = *(const uint32_t*)&sm[ALo + base];
                al[mt][1] = *(const uint32_t*)&sm[ALo + base + 8*SM_STRIDE];
                al[mt][2] = *(const uint32_t*)&sm[ALo + base + 8];
                al[mt][3] = *(const uint32_t*)&sm[ALo + base + 8*SM_STRIDE + 8];
            }
            uint32_t bh[8][2], bl[8][2];
            #pragma unroll
            for (int nt = 0; nt < 8; nt++) {
                int base = (wn + nt*8 + (lane >> 2)) * SM_STRIDE + ks + (lane & 3) * 2;
                bh[nt][0] = *(const uint32_t*)&sm[BHo + base];
                bh[nt][1] = *(const uint32_t*)&sm[BHo + base + 8];
                bl[nt][0] = *(const uint32_t*)&sm[BLo + base];
                bl[nt][1] = *(const uint32_t*)&sm[BLo + base + 8];
            }
            #pragma unroll
            for (int mt = 0; mt < 2; mt++)
                #pragma unroll
                for (int nt = 0; nt < 8; nt++) {
                    mma16816(acc[mt][nt], ah[mt], bh[nt]);   // hi*hi
                    mma16816(acc[mt][nt], ah[mt], bl[nt]);   // hi*lo
                    mma16816(acc[mt][nt], al[mt], bh[nt]);   // lo*hi
                }
        }
        __syncthreads();
        // ---- store prefetched chunk ----
        if (kb + 1 < nk) {
            if (AT) {
                #pragma unroll
                for (int i = 0; i < 4; i++) {
                    int k = 8*i + w;
                    #pragma unroll
                    for (int j = 0; j < 4; j++) {
                        int fl = lane + 32*j;
                        __half h, l; split2(pa[i*4+j], h, l);
                        sm[AHo + fl*SM_STRIDE + k] = h;
                        sm[ALo + fl*SM_STRIDE + k] = l;
                    }
                }
            } else {
                #pragma unroll
                for (int rr = 0; rr < 16; rr++) {
                    __half h, l; split2(pa[rr], h, l);
                    sm[AHo + (w*16+rr)*SM_STRIDE + lane] = h;
                    sm[ALo + (w*16+rr)*SM_STRIDE + lane] = l;
                }
            }
            #pragma unroll
            for (int i = 0; i < 4; i++) {
                int k = 8*i + w;
                #pragma unroll
                for (int j = 0; j < 4; j++) {
                    int nl = lane + 32*j;
                    __half h, l; split2(pb[i*4+j], h, l);
                    sm[BHo + nl*SM_STRIDE + k] = h;
                    sm[BLo + nl*SM_STRIDE + k] = l;
                }
            }
            __syncthreads();
        }
    }

    // ---- epilogue: bias + relu + store ----
    #pragma unroll
    for (int mt = 0; mt < 2; mt++) {
        #pragma unroll
        for (int nt = 0; nt < 8; nt++) {
            int col = n0 + wn + nt*8 + (lane & 3) * 2;
            float b0 = bias[col], b1 = bias[col+1];
            int r0 = m0 + wm + mt*16 + (lane >> 2);
            if (r0 < Md) {
                float2 o;
                o.x = fmaxf(acc[mt][nt][0] + b0, 0.f);
                o.y = fmaxf(acc[mt][nt][1] + b1, 0.f);
                *(float2*)(Cb + (size_t)r0 * DTd + col) = o;
            }
            int r1 = r0 + 8;
            if (r1 < Md) {
                float2 o;
                o.x = fmaxf(acc[mt][nt][2] + b0, 0.f);
                o.y = fmaxf(acc[mt][nt][3] + b1, 0.f);
                *(float2*)(Cb + (size_t)r1 * DTd + col) = o;
            }
        }
    }
}

// ---------------- top-k (matches jax.lax.top_k: ties -> lowest index) -----
__global__ void topk_kernel(const float* __restrict__ logits) {
    int b = blockIdx.x;
    const float* row = logits + b*Cd;
    __shared__ float sv[256];
    __shared__ int   si[256];
    __shared__ int   chosen[TK];
    int tid = threadIdx.x;
    for (int sel = 0; sel < TK; sel++) {
        float best = -INFINITY; int bi = 1 << 30;
        for (int i = tid; i < Cd; i += 256) {
            bool skip = false;
            for (int j = 0; j < sel; j++) if (chosen[j] == i) skip = true;
            if (skip) continue;
            float v = row[i];
            if (v > best || (v == best && i < bi)) { best = v; bi = i; }
        }
        sv[tid] = best; si[tid] = bi;
        __syncthreads();
        for (int s = 128; s > 0; s >>= 1) {
            if (tid < s) {
                if (sv[tid+s] > sv[tid] || (sv[tid+s] == sv[tid] && si[tid+s] < si[tid])) {
                    sv[tid] = sv[tid+s]; si[tid] = si[tid+s];
                }
            }
            __syncthreads();
        }
        if (tid == 0) chosen[sel] = si[0];
        __syncthreads();
    }
    if (tid < TK) g_topk[b*TK + tid] = chosen[tid];
}

// ---------------- gather + mean-pool word embeddings -----------------------
__global__ void gather_emb_kernel(const int* __restrict__ table,
                                  const float* __restrict__ w2v) {
    int bk = blockIdx.x;                 // 0..639
    int c  = g_topk[bk];
    int i0 = table[c*4+0], i1 = table[c*4+1], i2 = table[c*4+2], i3 = table[c*4+3];
    for (int d = threadIdx.x; d < DWd; d += blockDim.x)
        g_emb[bk*DWd + d] = 0.25f*(w2v[(size_t)i0*DWd+d] + w2v[(size_t)i1*DWd+d]
                                 + w2v[(size_t)i2*DWd+d] + w2v[(size_t)i3*DWd+d]);
}

// ---------------- fp32 GEMM (small): C = relu?(A @ B + bias) ---------------
__global__ void gemm_kernel(const float* __restrict__ A, const float* __restrict__ Bm,
                            const float* __restrict__ bias, float* __restrict__ Cm,
                            int Md, int Nd, int Kd, int relu)
{
    __shared__ float As[16][68];
    __shared__ float Bs[16][68];
    int m0 = blockIdx.y * 64, n0 = blockIdx.x * 64;
    int tid = threadIdx.x;
    int tx = tid & 15, ty = tid >> 4;
    float acc[4][4] = {};

    for (int k0 = 0; k0 < Kd; k0 += 16) {
        {
            int kk = tid & 15, mm0 = tid >> 4;
            #pragma unroll
            for (int r = 0; r < 4; r++) {
                int mm = mm0 + r*16;
                int k = k0 + kk, m = m0 + mm;
                As[kk][mm] = (k < Kd && m < Md) ? A[(size_t)m*Kd + k] : 0.f;
            }
        }
        {
            int nn = tid & 63, kk0 = tid >> 6;
            #pragma unroll
            for (int r = 0; r < 4; r++) {
                int kk = kk0 + r*4;
                int k = k0 + kk, n = n0 + nn;
                Bs[kk][nn] = (k < Kd && n < Nd) ? Bm[(size_t)k*Nd + n] : 0.f;
            }
        }
        __syncthreads();
        #pragma unroll
        for (int kk = 0; kk < 16; kk++) {
            float4 a4 = *(const float4*)&As[kk][ty*4];
            float4 b4 = *(const float4*)&Bs[kk][tx*4];
            float av[4] = {a4.x, a4.y, a4.z, a4.w};
            float bv[4] = {b4.x, b4.y, b4.z, b4.w};
            #pragma unroll
            for (int i = 0; i < 4; i++)
                #pragma unroll
                for (int j = 0; j < 4; j++)
                    acc[i][j] += av[i] * bv[j];
        }
        __syncthreads();
    }
    #pragma unroll
    for (int i = 0; i < 4; i++) {
        int m = m0 + ty*4 + i;
        if (m >= Md) continue;
        #pragma unroll
        for (int j = 0; j < 4; j++) {
            int n = n0 + tx*4 + j;
            if (n >= Nd) continue;
            float c = acc[i][j] + bias[n];
            if (relu) c = fmaxf(c, 0.f);
            Cm[(size_t)m*Nd + n] = c;
        }
    }
}

// ---------------- attention scores: s[b,f,k] = v[b,f,:] . cls[b,k,:] -------
__global__ void scores_kernel() {
    int b = blockIdx.y;
    __shared__ float cls_s[TK*DTd];      // 40 KB
    for (int i = threadIdx.x; i < TK*DTd; i += 256)
        cls_s[i] = g_cls[b*TK*DTd + i];
    __syncthreads();
    int w = threadIdx.x >> 5, lane = threadIdx.x & 31;
    int f0 = (blockIdx.x*8 + w) * 4;
    float acc[4][TK];
    #pragma unroll
    for (int j = 0; j < 4; j++)
        #pragma unroll
        for (int k = 0; k < TK; k++) acc[j][k] = 0.f;
    const float* vb = g_v + (size_t)b*Fd*DTd;
    for (int i = 0; i < 32; i++) {
        int t = lane + 32*i;
        float vv[4];
        #pragma unroll
        for (int j = 0; j < 4; j++)
            vv[j] = (f0+j < Fd) ? vb[(size_t)(f0+j)*DTd + t] : 0.f;
        #pragma unroll
        for (int k = 0; k < TK; k++) {
            float c = cls_s[k*DTd + t];
            #pragma unroll
            for (int j = 0; j < 4; j++) acc[j][k] += vv[j] * c;
        }
    }
    #pragma unroll
    for (int j = 0; j < 4; j++) {
        #pragma unroll
        for (int k = 0; k < TK; k++) {
            float r = acc[j][k];
            #pragma unroll
            for (int o = 16; o; o >>= 1) r += __shfl_xor_sync(0xffffffffu, r, o);
            if (lane == 0 && f0+j < Fd)
                g_s[((size_t)b*Fd + f0 + j)*TK + k] = r;
        }
    }
}

// ---------------- softmax over f per (b,k), in place -----------------------
__global__ void softmax_kernel() {
    int b = blockIdx.y, k = blockIdx.x;
    float* base = g_s + (size_t)b*Fd*TK + k;
    __shared__ float red[256];
    int tid = threadIdx.x;
    float mx = -INFINITY;
    for (int f = tid; f < Fd; f += 256) mx = fmaxf(mx, base[f*TK]);
    red[tid] = mx; __syncthreads();
    for (int s = 128; s > 0; s >>= 1) {
        if (tid < s) red[tid] = fmaxf(red[tid], red[tid+s]);
        __syncthreads();
    }
    mx = red[0]; __syncthreads();
    float sum = 0.f;
    for (int f = tid; f < Fd; f += 256) {
        float e = expf(base[f*TK] - mx);
        base[f*TK] = e;
        sum += e;
    }
    red[tid] = sum; __syncthreads();
    for (int s = 128; s > 0; s >>= 1) {
        if (tid < s) red[tid] += red[tid+s];
        __syncthreads();
    }
    float inv = 1.f / red[0];
    for (int f = tid; f < Fd; f += 256) base[f*TK] *= inv;
}

// ---------------- bap[b,d] = sum_k cls[b,k,d] * sum_f att[b,f,k]*v[b,f,d] --
__global__ void bap_kernel() {
    int b = blockIdx.y;
    int d = blockIdx.x*256 + threadIdx.x;     // 0..1023
    __shared__ float att_s[Fd*12];            // padded to 12 for aligned float4
    for (int i = threadIdx.x; i < Fd*12; i += 256) {
        int f = i / 12, k = i % 12;
        att_s[i] = (k < TK) ? g_s[((size_t)b*Fd + f)*TK + k] : 0.f;
    }
    __syncthreads();
    float acc[TK] = {};
    const float* vb = g_v + (size_t)b*Fd*DTd + d;
    for (int f = 0; f < Fd; f++) {
        float vv = vb[(size_t)f*DTd];
        const float4* ap = (const float4*)&att_s[f*12];
        float4 a0 = ap[0], a1 = ap[1], a2 = ap[2];
        acc[0] += vv*a0.x; acc[1] += vv*a0.y; acc[2] += vv*a0.z; acc[3] += vv*a0.w;
        acc[4] += vv*a1.x; acc[5] += vv*a1.y; acc[6] += vv*a1.z; acc[7] += vv*a1.w;
        acc[8] += vv*a2.x; acc[9] += vv*a2.y;
    }
    float r = 0.f;
    #pragma unroll
    for (int k = 0; k < TK; k++)
        r += acc[k] * g_cls[((size_t)b*TK + k)*DTd + d];
    g_bap[b*DTd + d] = r;
}

// ---------------- final FC (DT->K) + scatter into [B, C] output ------------
__global__ void fc_scatter_kernel(const float* __restrict__ W_fc,
                                  const float* __restrict__ b_fc,
                                  float* __restrict__ out) {
    int b = blockIdx.x;
    int wid = threadIdx.x >> 5, lane = threadIdx.x & 31;   // 10 warps
    if (wid < TK) {
        float s = 0.f;
        for (int d = lane; d < DTd; d += 32)
            s += g_bap2[b*DTd + d] * W_fc[d*TK + wid];
        #pragma unroll
        for (int o = 16; o; o >>= 1) s += __shfl_xor_sync(0xffffffffu, s, o);
        if (lane == 0)
            out[(size_t)b*Cd + g_topk[b*TK + wid]] = s + b_fc[wid];
    }
}

// ---------------- launch ----------------------------------------------------
extern "C" void kernel_launch(void* const* d_in, const int* in_sizes, int n_in,
                              void* d_out, int out_size) {
    const float* ftm    = (const float*)d_in[0];
    const float* logits = (const float*)d_in[1];
    /* d_in[2] = labels (unused by reference) */
    const int*   table  = (const int*)  d_in[3];
    const float* w2v    = (const float*)d_in[4];
    const float* W_emb  = (const float*)d_in[5];
    const float* b_emb  = (const float*)d_in[6];
    const float* W_cls  = (const float*)d_in[7];
    const float* b_cls  = (const float*)d_in[8];
    const float* W_v    = (const float*)d_in[9];
    const float* b_v    = (const float*)d_in[10];
    const float* W_bap  = (const float*)d_in[11];
    const float* b_bap  = (const float*)d_in[12];
    const float* W_fc   = (const float*)d_in[13];
    const float* b_fc   = (const float*)d_in[14];
    float* out = (float*)d_out;

    float *p_emb, *p_cls1, *p_cls, *p_v, *p_bap, *p_bap2;
    cudaGetSymbolAddress((void**)&p_emb,  g_emb);
    cudaGetSymbolAddress((void**)&p_cls1, g_cls1);
    cudaGetSymbolAddress((void**)&p_cls,  g_cls);
    cudaGetSymbolAddress((void**)&p_v,    g_v);
    cudaGetSymbolAddress((void**)&p_bap,  g_bap);
    cudaGetSymbolAddress((void**)&p_bap2, g_bap2);

    cudaMemsetAsync(d_out, 0, (size_t)out_size * sizeof(float), 0);

    topk_kernel<<<Bsz, 256>>>(logits);
    gather_emb_kernel<<<Bsz*TK, 128>>>(table, w2v);

    // cls1 = relu(emb @ W_emb + b_emb)       [640 x 1024, K=300]  (tensor)
    tgemm_kernel<0><<<dim3(8, 5, 1), 256>>>(p_emb,  W_emb, b_emb, p_cls1, Bsz*TK, DWd);
    // cls  = relu(cls1 @ W_cls + b_cls)      [640 x 1024, K=1024] (tensor)
    tgemm_kernel<0><<<dim3(8, 5, 1), 256>>>(p_cls1, W_cls, b_cls, p_cls,  Bsz*TK, DTd);
    // v = relu(ftm^T @ W_v + b_v)            64 x [676 x 1024, K=768] (tensor)
    tgemm_kernel<1><<<dim3(8, 6, Bsz), 256>>>(ftm, W_v, b_v, p_v, Fd, DFd);

    scores_kernel <<<dim3(22, Bsz), 256>>>();
    softmax_kernel<<<dim3(TK, Bsz), 256>>>();
    bap_kernel    <<<dim3(4,  Bsz), 256>>>();

    // bap2 = relu(bap @ W_bap + b_bap)       [64 x 1024, K=1024] (fp32, tiny)
    gemm_kernel<<<dim3(16, 1, 1), 256>>>(p_bap, W_bap, b_bap, p_bap2, Bsz, DTd, DTd, 1);

    fc_scatter_kernel<<<Bsz, 320>>>(W_fc, b_fc, out);
}

// round 5
// speedup vs baseline: 1.6565x; 1.0002x over previous
#include <cuda_runtime.h>
#include <cuda_fp16.h>
#include <math.h>
#include <stdint.h>

#define Bsz 64
#define DFd 768
#define Fd  676
#define Cd  3129
#define DWd 300
#define DTd 1024
#define TK  10

// ---------------- device scratch (static, allocation-free) ----------------
__device__ int   g_topk[Bsz*TK];
__device__ float g_emb [Bsz*TK*DWd];
__device__ float g_cls1[Bsz*TK*DTd];
__device__ float g_cls [Bsz*TK*DTd];
__device__ float g_v   [(size_t)Bsz*Fd*DTd];   // 177 MB
__device__ float g_s   [Bsz*Fd*TK];
__device__ float g_bap [Bsz*DTd];
__device__ float g_bap2[Bsz*DTd];

// ================= fp16x2-split tensor-core GEMM (mma.sync HMMA) ==========
// C[m][n] = relu( sum_k A[m][k] * B[k][n] + bias[n] ),  N = 1024 fixed.
// AT=1: A stored [K][M] (m contiguous) and batched over blockIdx.z.
// Each fp32 x is split x = hi + lo (fp16); product emulated by
// hi*hi + hi*lo + lo*hi accumulated in fp32 (error ~2^-22).
#define SM_STRIDE 34          // halves per row (17 words -> conflict-free)
#define AHo 0
#define ALo (128*SM_STRIDE)
#define BHo (2*128*SM_STRIDE)
#define BLo (3*128*SM_STRIDE)

__device__ __forceinline__ void mma16816(float* c, const uint32_t* a, const uint32_t* b) {
    asm volatile(
        "mma.sync.aligned.m16n8k16.row.col.f32.f16.f16.f32 "
        "{%0,%1,%2,%3}, {%4,%5,%6,%7}, {%8,%9}, {%0,%1,%2,%3};"
        : "+f"(c[0]), "+f"(c[1]), "+f"(c[2]), "+f"(c[3])
        : "r"(a[0]), "r"(a[1]), "r"(a[2]), "r"(a[3]), "r"(b[0]), "r"(b[1]));
}
__device__ __forceinline__ void split2(float x, __half& h, __half& l) {
    h = __float2half_rn(x);
    l = __float2half_rn(x - __half2float(h));
}

template<int AT>
__global__ void __launch_bounds__(256)
tgemm_kernel(const float* __restrict__ A, const float* __restrict__ Bm,
             const float* __restrict__ bias, float* __restrict__ Cm,
             int Md, int Kd)
{
    __shared__ __half sm[4*128*SM_STRIDE];   // 34816 B
    int tid  = threadIdx.x;
    int w    = tid >> 5, lane = tid & 31;
    int m0   = blockIdx.y * 128, n0 = blockIdx.x * 128;
    const float* Ab = A;
    float* Cb = Cm;
    if (AT) {
        Ab = A  + (size_t)blockIdx.z * Kd * Md;
        Cb = Cm + (size_t)blockIdx.z * Md * DTd;
    }
    int nk = (Kd + 31) / 32;

    float pa[16], pb[16];
    // ---- prologue: load chunk 0 ----
    {
        int k0 = 0;
        if (AT) {
            #pragma unroll
            for (int i = 0; i < 4; i++) {
                int k = 8*i + w;
                const float* col = Ab + (size_t)(k0 + k) * Md + m0;
                #pragma unroll
                for (int j = 0; j < 4; j++) {
                    int fl = lane + 32*j;
                    pa[i*4+j] = (k0+k < Kd && m0+fl < Md) ? col[fl] : 0.f;
                }
            }
        } else {
            #pragma unroll
            for (int rr = 0; rr < 16; rr++) {
                int m = m0 + w*16 + rr;
                pa[rr] = (m < Md && k0+lane < Kd) ? Ab[(size_t)m*Kd + k0 + lane] : 0.f;
            }
        }
        #pragma unroll
        for (int i = 0; i < 4; i++) {
            int k = 8*i + w;
            const float* col = Bm + (size_t)(k0 + k) * DTd + n0;
            #pragma unroll
            for (int j = 0; j < 4; j++)
                pb[i*4+j] = (k0+k < Kd) ? col[lane + 32*j] : 0.f;
        }
    }
    // store chunk 0
    {
        if (AT) {
            #pragma unroll
            for (int i = 0; i < 4; i++) {
                int k = 8*i + w;
                #pragma unroll
                for (int j = 0; j < 4; j++) {
                    int fl = lane + 32*j;
                    __half h, l; split2(pa[i*4+j], h, l);
                    sm[AHo + fl*SM_STRIDE + k] = h;
                    sm[ALo + fl*SM_STRIDE + k] = l;
                }
            }
        } else {
            #pragma unroll
            for (int rr = 0; rr < 16; rr++) {
                __half h, l; split2(pa[rr], h, l);
                sm[AHo + (w*16+rr)*SM_STRIDE + lane] = h;
                sm[ALo + (w*16+rr)*SM_STRIDE + lane] = l;
            }
        }
        #pragma unroll
        for (int i = 0; i < 4; i++) {
            int k = 8*i + w;
            #pragma unroll
            for (int j = 0; j < 4; j++) {
                int nl = lane + 32*j;
                __half h, l; split2(pb[i*4+j], h, l);
                sm[BHo + nl*SM_STRIDE + k] = h;
                sm[BLo + nl*SM_STRIDE + k] = l;
            }
        }
    }
    __syncthreads();

    int wm = (w & 3) * 32;          // warp m offset in tile
    int wn = (w >> 2) * 64;         // warp n offset in tile
    float acc[2][8][4];
    #pragma unroll
    for (int mt = 0; mt < 2; mt++)
        #pragma unroll
        for (int nt = 0; nt < 8; nt++)
            #pragma unroll
            for (int q = 0; q < 4; q++) acc[mt][nt][q] = 0.f;

    for (int kb = 0; kb < nk; kb++) {
        // ---- prefetch next chunk into registers ----
        if (kb + 1 < nk) {
            int k0 = (kb + 1) * 32;
            if (AT) {
                #pragma unroll
                for (int i = 0; i < 4; i++) {
                    int k = 8*i + w;
                    const float* col = Ab + (size_t)(k0 + k) * Md + m0;
                    #pragma unroll
                    for (int j = 0; j < 4; j++) {
                        int fl = lane + 32*j;
                        pa[i*4+j] = (k0+k < Kd && m0+fl < Md) ? col[fl] : 0.f;
                    }
                }
            } else {
                #pragma unroll
                for (int rr = 0; rr < 16; rr++) {
                    int m = m0 + w*16 + rr;
                    pa[rr] = (m < Md && k0+lane < Kd) ? Ab[(size_t)m*Kd + k0 + lane] : 0.f;
                }
            }
            #pragma unroll
            for (int i = 0; i < 4; i++) {
                int k = 8*i + w;
                const float* col = Bm + (size_t)(k0 + k) * DTd + n0;
                #pragma unroll
                for (int j = 0; j < 4; j++)
                    pb[i*4+j] = (k0+k < Kd) ? col[lane + 32*j] : 0.f;
            }
        }
        // ---- compute on current smem chunk ----
        #pragma unroll
        for (int ks = 0; ks < 32; ks += 16) {
            uint32_t ah[2][4], al[2][4];
            #pragma unroll
            for (int mt = 0; mt < 2; mt++) {
                int base = (wm + mt*16 + (lane >> 2)) * SM_STRIDE + ks + (lane & 3) * 2;
                ah[mt][0] = *(const uint32_t*)&sm[AHo + base];
                ah[mt][1] = *(const uint32_t*)&sm[AHo + base + 8*SM_STRIDE];
                ah[mt][2] = *(const uint32_t*)&sm[AHo + base + 8];
                ah[mt][3] = *(const uint32_t*)&sm[AHo + base + 8*SM_STRIDE + 8];
                al[mt][0] = *(const uint32_t*)&sm[ALo + base];
                al[mt][1] = *(const uint32_t*)&sm[ALo + base + 8*SM_STRIDE];
                al[mt][2] = *(const uint32_t*)&sm[ALo + base + 8];
                al[mt][3] = *(const uint32_t*)&sm[ALo + base + 8*SM_STRIDE + 8];
            }
            uint32_t bh[8][2], bl[8][2];
            #pragma unroll
            for (int nt = 0; nt < 8; nt++) {
                int base = (wn + nt*8 + (lane >> 2)) * SM_STRIDE + ks + (lane & 3) * 2;
                bh[nt][0] = *(const uint32_t*)&sm[BHo + base];
                bh[nt][1] = *(const uint32_t*)&sm[BHo + base + 8];
                bl[nt][0] = *(const uint32_t*)&sm[BLo + base];
                bl[nt][1] = *(const uint32_t*)&sm[BLo + base + 8];
            }
            #pragma unroll
            for (int mt = 0; mt < 2; mt++)
                #pragma unroll
                for (int nt = 0; nt < 8; nt++) {
                    mma16816(acc[mt][nt], ah[mt], bh[nt]);   // hi*hi
                    mma16816(acc[mt][nt], ah[mt], bl[nt]);   // hi*lo
                    mma16816(acc[mt][nt], al[mt], bh[nt]);   // lo*hi
                }
        }
        __syncthreads();
        // ---- store prefetched chunk ----
        if (kb + 1 < nk) {
            if (AT) {
                #pragma unroll
                for (int i = 0; i < 4; i++) {
                    int k = 8*i + w;
                    #pragma unroll
                    for (int j = 0; j < 4; j++) {
                        int fl = lane + 32*j;
                        __half h, l; split2(pa[i*4+j], h, l);
                        sm[AHo + fl*SM_STRIDE + k] = h;
                        sm[ALo + fl*SM_STRIDE + k] = l;
                    }
                }
            } else {
                #pragma unroll
                for (int rr = 0; rr < 16; rr++) {
                    __half h, l; split2(pa[rr], h, l);
                    sm[AHo + (w*16+rr)*SM_STRIDE + lane] = h;
                    sm[ALo + (w*16+rr)*SM_STRIDE + lane] = l;
                }
            }
            #pragma unroll
            for (int i = 0; i < 4; i++) {
                int k = 8*i + w;
                #pragma unroll
                for (int j = 0; j < 4; j++) {
                    int nl = lane + 32*j;
                    __half h, l; split2(pb[i*4+j], h, l);
                    sm[BHo + nl*SM_STRIDE + k] = h;
                    sm[BLo + nl*SM_STRIDE + k] = l;
                }
            }
            __syncthreads();
        }
    }

    // ---- epilogue: bias + relu + store ----
    #pragma unroll
    for (int mt = 0; mt < 2; mt++) {
        #pragma unroll
        for (int nt = 0; nt < 8; nt++) {
            int col = n0 + wn + nt*8 + (lane & 3) * 2;
            float b0 = bias[col], b1 = bias[col+1];
            int r0 = m0 + wm + mt*16 + (lane >> 2);
            if (r0 < Md) {
                float2 o;
                o.x = fmaxf(acc[mt][nt][0] + b0, 0.f);
                o.y = fmaxf(acc[mt][nt][1] + b1, 0.f);
                *(float2*)(Cb + (size_t)r0 * DTd + col) = o;
            }
            int r1 = r0 + 8;
            if (r1 < Md) {
                float2 o;
                o.x = fmaxf(acc[mt][nt][2] + b0, 0.f);
                o.y = fmaxf(acc[mt][nt][3] + b1, 0.f);
                *(float2*)(Cb + (size_t)r1 * DTd + col) = o;
            }
        }
    }
}

// ---------------- top-k (matches jax.lax.top_k: ties -> lowest index) -----
__global__ void topk_kernel(const float* __restrict__ logits) {
    int b = blockIdx.x;
    const float* row = logits + b*Cd;
    __shared__ float sv[256];
    __shared__ int   si[256];
    __shared__ int   chosen[TK];
    int tid = threadIdx.x;
    for (int sel = 0; sel < TK; sel++) {
        float best = -INFINITY; int bi = 1 << 30;
        for (int i = tid; i < Cd; i += 256) {
            bool skip = false;
            for (int j = 0; j < sel; j++) if (chosen[j] == i) skip = true;
            if (skip) continue;
            float v = row[i];
            if (v > best || (v == best && i < bi)) { best = v; bi = i; }
        }
        sv[tid] = best; si[tid] = bi;
        __syncthreads();
        for (int s = 128; s > 0; s >>= 1) {
            if (tid < s) {
                if (sv[tid+s] > sv[tid] || (sv[tid+s] == sv[tid] && si[tid+s] < si[tid])) {
                    sv[tid] = sv[tid+s]; si[tid] = si[tid+s];
                }
            }
            __syncthreads();
        }
        if (tid == 0) chosen[sel] = si[0];
        __syncthreads();
    }
    if (tid < TK) g_topk[b*TK + tid] = chosen[tid];
}

// ---------------- gather + mean-pool word embeddings -----------------------
__global__ void gather_emb_kernel(const int* __restrict__ table,
                                  const float* __restrict__ w2v) {
    int bk = blockIdx.x;                 // 0..639
    int c  = g_topk[bk];
    int i0 = table[c*4+0], i1 = table[c*4+1], i2 = table[c*4+2], i3 = table[c*4+3];
    for (int d = threadIdx.x; d < DWd; d += blockDim.x)
        g_emb[bk*DWd + d] = 0.25f*(w2v[(size_t)i0*DWd+d] + w2v[(size_t)i1*DWd+d]
                                 + w2v[(size_t)i2*DWd+d] + w2v[(size_t)i3*DWd+d]);
}

// ---------------- fp32 GEMM (small): C = relu?(A @ B + bias) ---------------
__global__ void gemm_kernel(const float* __restrict__ A, const float* __restrict__ Bm,
                            const float* __restrict__ bias, float* __restrict__ Cm,
                            int Md, int Nd, int Kd, int relu)
{
    __shared__ float As[16][68];
    __shared__ float Bs[16][68];
    int m0 = blockIdx.y * 64, n0 = blockIdx.x * 64;
    int tid = threadIdx.x;
    int tx = tid & 15, ty = tid >> 4;
    float acc[4][4] = {};

    for (int k0 = 0; k0 < Kd; k0 += 16) {
        {
            int kk = tid & 15, mm0 = tid >> 4;
            #pragma unroll
            for (int r = 0; r < 4; r++) {
                int mm = mm0 + r*16;
                int k = k0 + kk, m = m0 + mm;
                As[kk][mm] = (k < Kd && m < Md) ? A[(size_t)m*Kd + k] : 0.f;
            }
        }
        {
            int nn = tid & 63, kk0 = tid >> 6;
            #pragma unroll
            for (int r = 0; r < 4; r++) {
                int kk = kk0 + r*4;
                int k = k0 + kk, n = n0 + nn;
                Bs[kk][nn] = (k < Kd && n < Nd) ? Bm[(size_t)k*Nd + n] : 0.f;
            }
        }
        __syncthreads();
        #pragma unroll
        for (int kk = 0; kk < 16; kk++) {
            float4 a4 = *(const float4*)&As[kk][ty*4];
            float4 b4 = *(const float4*)&Bs[kk][tx*4];
            float av[4] = {a4.x, a4.y, a4.z, a4.w};
            float bv[4] = {b4.x, b4.y, b4.z, b4.w};
            #pragma unroll
            for (int i = 0; i < 4; i++)
                #pragma unroll
                for (int j = 0; j < 4; j++)
                    acc[i][j] += av[i] * bv[j];
        }
        __syncthreads();
    }
    #pragma unroll
    for (int i = 0; i < 4; i++) {
        int m = m0 + ty*4 + i;
        if (m >= Md) continue;
        #pragma unroll
        for (int j = 0; j < 4; j++) {
            int n = n0 + tx*4 + j;
            if (n >= Nd) continue;
            float c = acc[i][j] + bias[n];
            if (relu) c = fmaxf(c, 0.f);
            Cm[(size_t)m*Nd + n] = c;
        }
    }
}

// ---------------- attention scores: s[b,f,k] = v[b,f,:] . cls[b,k,:] -------
__global__ void scores_kernel() {
    int b = blockIdx.y;
    __shared__ float cls_s[TK*DTd];      // 40 KB
    for (int i = threadIdx.x; i < TK*DTd; i += 256)
        cls_s[i] = g_cls[b*TK*DTd + i];
    __syncthreads();
    int w = threadIdx.x >> 5, lane = threadIdx.x & 31;
    int f0 = (blockIdx.x*8 + w) * 4;
    float acc[4][TK];
    #pragma unroll
    for (int j = 0; j < 4; j++)
        #pragma unroll
        for (int k = 0; k < TK; k++) acc[j][k] = 0.f;
    const float* vb = g_v + (size_t)b*Fd*DTd;
    for (int i = 0; i < 32; i++) {
        int t = lane + 32*i;
        float vv[4];
        #pragma unroll
        for (int j = 0; j < 4; j++)
            vv[j] = (f0+j < Fd) ? vb[(size_t)(f0+j)*DTd + t] : 0.f;
        #pragma unroll
        for (int k = 0; k < TK; k++) {
            float c = cls_s[k*DTd + t];
            #pragma unroll
            for (int j = 0; j < 4; j++) acc[j][k] += vv[j] * c;
        }
    }
    #pragma unroll
    for (int j = 0; j < 4; j++) {
        #pragma unroll
        for (int k = 0; k < TK; k++) {
            float r = acc[j][k];
            #pragma unroll
            for (int o = 16; o; o >>= 1) r += __shfl_xor_sync(0xffffffffu, r, o);
            if (lane == 0 && f0+j < Fd)
                g_s[((size_t)b*Fd + f0 + j)*TK + k] = r;
        }
    }
}

// ---------------- softmax over f per (b,k), in place -----------------------
__global__ void softmax_kernel() {
    int b = blockIdx.y, k = blockIdx.x;
    float* base = g_s + (size_t)b*Fd*TK + k;
    __shared__ float red[256];
    int tid = threadIdx.x;
    float mx = -INFINITY;
    for (int f = tid; f < Fd; f += 256) mx = fmaxf(mx, base[f*TK]);
    red[tid] = mx; __syncthreads();
    for (int s = 128; s > 0; s >>= 1) {
        if (tid < s) red[tid] = fmaxf(red[tid], red[tid+s]);
        __syncthreads();
    }
    mx = red[0]; __syncthreads();
    float sum = 0.f;
    for (int f = tid; f < Fd; f += 256) {
        float e = expf(base[f*TK] - mx);
        base[f*TK] = e;
        sum += e;
    }
    red[tid] = sum; __syncthreads();
    for (int s = 128; s > 0; s >>= 1) {
        if (tid < s) red[tid] += red[tid+s];
        __syncthreads();
    }
    float inv = 1.f / red[0];
    for (int f = tid; f < Fd; f += 256) base[f*TK] *= inv;
}

// ---------------- bap[b,d] = sum_k cls[b,k,d] * sum_f att[b,f,k]*v[b,f,d] --
__global__ void bap_kernel() {
    int b = blockIdx.y;
    int d = blockIdx.x*256 + threadIdx.x;     // 0..1023
    __shared__ float att_s[Fd*12];            // padded to 12 for aligned float4
    for (int i = threadIdx.x; i < Fd*12; i += 256) {
        int f = i / 12, k = i % 12;
        att_s[i] = (k < TK) ? g_s[((size_t)b*Fd + f)*TK + k] : 0.f;
    }
    __syncthreads();
    float acc[TK] = {};
    const float* vb = g_v + (size_t)b*Fd*DTd + d;
    for (int f = 0; f < Fd; f++) {
        float vv = vb[(size_t)f*DTd];
        const float4* ap = (const float4*)&att_s[f*12];
        float4 a0 = ap[0], a1 = ap[1], a2 = ap[2];
        acc[0] += vv*a0.x; acc[1] += vv*a0.y; acc[2] += vv*a0.z; acc[3] += vv*a0.w;
        acc[4] += vv*a1.x; acc[5] += vv*a1.y; acc[6] += vv*a1.z; acc[7] += vv*a1.w;
        acc[8] += vv*a2.x; acc[9] += vv*a2.y;
    }
    float r = 0.f;
    #pragma unroll
    for (int k = 0; k < TK; k++)
        r += acc[k] * g_cls[((size_t)b*TK + k)*DTd + d];
    g_bap[b*DTd + d] = r;
}

// ---------------- final FC (DT->K) + scatter into [B, C] output ------------
__global__ void fc_scatter_kernel(const float* __restrict__ W_fc,
                                  const float* __restrict__ b_fc,
                                  float* __restrict__ out) {
    int b = blockIdx.x;
    int wid = threadIdx.x >> 5, lane = threadIdx.x & 31;   // 10 warps
    if (wid < TK) {
        float s = 0.f;
        for (int d = lane; d < DTd; d += 32)
            s += g_bap2[b*DTd + d] * W_fc[d*TK + wid];
        #pragma unroll
        for (int o = 16; o; o >>= 1) s += __shfl_xor_sync(0xffffffffu, s, o);
        if (lane == 0)
            out[(size_t)b*Cd + g_topk[b*TK + wid]] = s + b_fc[wid];
    }
}

// ---------------- launch ----------------------------------------------------
extern "C" void kernel_launch(void* const* d_in, const int* in_sizes, int n_in,
                              void* d_out, int out_size) {
    const float* ftm    = (const float*)d_in[0];
    const float* logits = (const float*)d_in[1];
    /* d_in[2] = labels (unused by reference) */
    const int*   table  = (const int*)  d_in[3];
    const float* w2v    = (const float*)d_in[4];
    const float* W_emb  = (const float*)d_in[5];
    const float* b_emb  = (const float*)d_in[6];
    const float* W_cls  = (const float*)d_in[7];
    const float* b_cls  = (const float*)d_in[8];
    const float* W_v    = (const float*)d_in[9];
    const float* b_v    = (const float*)d_in[10];
    const float* W_bap  = (const float*)d_in[11];
    const float* b_bap  = (const float*)d_in[12];
    const float* W_fc   = (const float*)d_in[13];
    const float* b_fc   = (const float*)d_in[14];
    float* out = (float*)d_out;

    float *p_emb, *p_cls1, *p_cls, *p_v, *p_bap, *p_bap2;
    cudaGetSymbolAddress((void**)&p_emb,  g_emb);
    cudaGetSymbolAddress((void**)&p_cls1, g_cls1);
    cudaGetSymbolAddress((void**)&p_cls,  g_cls);
    cudaGetSymbolAddress((void**)&p_v,    g_v);
    cudaGetSymbolAddress((void**)&p_bap,  g_bap);
    cudaGetSymbolAddress((void**)&p_bap2, g_bap2);

    cudaMemsetAsync(d_out, 0, (size_t)out_size * sizeof(float), 0);

    topk_kernel<<<Bsz, 256>>>(logits);
    gather_emb_kernel<<<Bsz*TK, 128>>>(table, w2v);

    // cls1 = relu(emb @ W_emb + b_emb)       [640 x 1024, K=300]  (tensor)
    tgemm_kernel<0><<<dim3(8, 5, 1), 256>>>(p_emb,  W_emb, b_emb, p_cls1, Bsz*TK, DWd);
    // cls  = relu(cls1 @ W_cls + b_cls)      [640 x 1024, K=1024] (tensor)
    tgemm_kernel<0><<<dim3(8, 5, 1), 256>>>(p_cls1, W_cls, b_cls, p_cls,  Bsz*TK, DTd);
    // v = relu(ftm^T @ W_v + b_v)            64 x [676 x 1024, K=768] (tensor)
    tgemm_kernel<1><<<dim3(8, 6, Bsz), 256>>>(ftm, W_v, b_v, p_v, Fd, DFd);

    scores_kernel <<<dim3(22, Bsz), 256>>>();
    softmax_kernel<<<dim3(TK, Bsz), 256>>>();
    bap_kernel    <<<dim3(4,  Bsz), 256>>>();

    // bap2 = relu(bap @ W_bap + b_bap)       [64 x 1024, K=1024] (fp32, tiny)
    gemm_kernel<<<dim3(16, 1, 1), 256>>>(p_bap, W_bap, b_bap, p_bap2, Bsz, DTd, DTd, 1);

    fc_scatter_kernel<<<Bsz, 320>>>(W_fc, b_fc, out);
}